// round 6
// baseline (speedup 1.0000x reference)
#include <cuda_runtime.h>

// ---------------------------------------------------------------------------
// WCT: whitening-coloring transform.
//   B=8, C=512, H=W=64, G=8  ->  NB = G*B = 64 batches, each a contiguous
//   [NM=64, HW=4096] fp32 matrix (reshape of (B,C,H,W) is a pure view).
// Pipeline:
//   K1: partial Grams (split-k x8) + partial row sums for c_A and s_B
//   K2: cov = (Gram - HW*mu*mu^T)/(HW-1) + eps*I ; coupled Newton-Schulz x10
//       -> stores cov_c^{-1/2} (w=0) and cov_b^{1/2} (w=1)
//   K3: M = cov_b^{1/2} @ cov_c^{-1/2};  v = mu_B - M*mu_A
//   K4: out = alpha*(M @ c_A + v) + (1-alpha)*c_A
// ---------------------------------------------------------------------------

#define NM 64
#define HW 4096
#define NB 64
#define KSPLIT 8
#define KCHUNK (HW / KSPLIT)   // 512
#define NSI 10
#define EPSV 1e-5f

// Scratch (device globals: no allocation inside kernel_launch).
__device__ __align__(16) float g_gram[KSPLIT][2][NB][NM * NM]; // 16 MB
__device__ __align__(16) float g_rows[KSPLIT][2][NB][NM];
__device__ __align__(16) float g_mean[2][NB][NM];
__device__ __align__(16) float g_ns[2][NB][NM * NM];           // 2 MB
__device__ __align__(16) float g_M[NB][NM * NM];               // 1 MB
__device__ __align__(16) float g_v[NB][NM];

// ---------------------------------------------------------------------------
// K1: partial Gram + row sums. grid = KSPLIT*128, block = 256.
// blockIdx: low 7 bits = pair (which*64 + batch), high bits = k-chunk.
// ---------------------------------------------------------------------------
__global__ __launch_bounds__(256)
void k_gram(const float* __restrict__ cA, const float* __restrict__ sB)
{
    const int pair  = blockIdx.x & 127;
    const int chunk = blockIdx.x >> 7;
    const int which = pair >> 6;
    const int b     = pair & 63;
    const float* __restrict__ X = (which ? sB : cA) + (size_t)b * NM * HW;
    const int k0base = chunk * KCHUNK;

    __shared__ __align__(16) float t[NM][65];   // [row][k], padded

    const int tid = threadIdx.x;
    const int tx = tid & 15, ty = tid >> 4;
    const int ry = ty * 4, rx = tx * 4;

    float acc[4][4];
#pragma unroll
    for (int i = 0; i < 4; i++)
#pragma unroll
        for (int j = 0; j < 4; j++) acc[i][j] = 0.f;
    float rowAcc = 0.f;

    for (int kc = 0; kc < KCHUNK; kc += 64) {
        __syncthreads();   // previous tile fully consumed
#pragma unroll
        for (int l = 0; l < 4; l++) {
            int idx = tid + l * 256;       // 0..1023
            int r   = idx >> 4;            // 0..63
            int c4  = (idx & 15) * 4;      // 0..60
            float4 v = *reinterpret_cast<const float4*>(
                X + (size_t)r * HW + k0base + kc + c4);
            t[r][c4 + 0] = v.x; t[r][c4 + 1] = v.y;
            t[r][c4 + 2] = v.z; t[r][c4 + 3] = v.w;
        }
        __syncthreads();

#pragma unroll 4
        for (int k = 0; k < 64; k++) {
            float a0 = t[ry + 0][k], a1 = t[ry + 1][k];
            float a2 = t[ry + 2][k], a3 = t[ry + 3][k];
            float b0 = t[rx + 0][k], b1 = t[rx + 1][k];
            float b2 = t[rx + 2][k], b3 = t[rx + 3][k];
            acc[0][0] += a0 * b0; acc[0][1] += a0 * b1;
            acc[0][2] += a0 * b2; acc[0][3] += a0 * b3;
            acc[1][0] += a1 * b0; acc[1][1] += a1 * b1;
            acc[1][2] += a1 * b2; acc[1][3] += a1 * b3;
            acc[2][0] += a2 * b0; acc[2][1] += a2 * b1;
            acc[2][2] += a2 * b2; acc[2][3] += a2 * b3;
            acc[3][0] += a3 * b0; acc[3][1] += a3 * b1;
            acc[3][2] += a3 * b2; acc[3][3] += a3 * b3;
        }
        // row sums (64 threads, cheap vs the 4096-cycle FMA block above)
        if (tid < 64) {
            float s = 0.f;
#pragma unroll 16
            for (int k = 0; k < 64; k++) s += t[tid][k];
            rowAcc += s;
        }
    }

    float* __restrict__ go = g_gram[chunk][which][b];
#pragma unroll
    for (int i = 0; i < 4; i++)
#pragma unroll
        for (int j = 0; j < 4; j++)
            go[(ry + i) * NM + rx + j] = acc[i][j];
    if (tid < 64) g_rows[chunk][which][b][tid] = rowAcc;
}

// ---------------------------------------------------------------------------
// K2: cov assembly + coupled Newton-Schulz. grid = 128 (which*64+b), block = 512.
// Each thread owns a 2x4 output block: rows ty*2..+1, cols tx*4..+3.
// ---------------------------------------------------------------------------
__global__ __launch_bounds__(512)
void k_ns()
{
    const int w = blockIdx.x >> 6;
    const int b = blockIdx.x & 63;

    __shared__ __align__(16) float sY[NM * NM];
    __shared__ __align__(16) float sZ[NM * NM];
    __shared__ __align__(16) float sT[NM * NM];

    const int tid = threadIdx.x;
    const int tx = tid & 15, ty = tid >> 4;   // ty: 0..31
    const int r0 = ty * 2, c0 = tx * 4;

    // means (into sT[0..63] temporarily, and to global for K3/K4)
    if (tid < NM) {
        float s = 0.f;
#pragma unroll
        for (int ch = 0; ch < KSPLIT; ch++) s += g_rows[ch][w][b][tid];
        float m = s * (1.f / (float)HW);
        sT[tid] = m;
        g_mean[w][b][tid] = m;
    }
    __syncthreads();

    // cov into sY, accumulate Frobenius^2
    float sq = 0.f;
#pragma unroll
    for (int i = 0; i < 2; i++) {
        float mr = sT[r0 + i];
#pragma unroll
        for (int j = 0; j < 4; j++) {
            int r = r0 + i, c = c0 + j;
            int idx = r * NM + c;
            float g = 0.f;
#pragma unroll
            for (int ch = 0; ch < KSPLIT; ch++) g += g_gram[ch][w][b][idx];
            float cv = (g - (float)HW * mr * sT[c]) * (1.f / (float)(HW - 1));
            if (r == c) cv += EPSV;
            sY[idx] = cv;
            sq += cv * cv;
        }
    }
    __syncthreads();              // done reading means from sT
    sZ[tid] = sq;                 // reduce Frobenius^2 in sZ
    __syncthreads();
    for (int s = 256; s > 0; s >>= 1) {
        if (tid < s) sZ[tid] += sZ[tid + s];
        __syncthreads();
    }
    const float norm = sqrtf(sZ[0]);
    const float invn = 1.f / norm;
    __syncthreads();              // everyone read sZ[0]; safe to overwrite

    // Y = A/norm ; Z = I
#pragma unroll
    for (int i = 0; i < 2; i++)
#pragma unroll
        for (int j = 0; j < 4; j++) {
            int r = r0 + i, c = c0 + j;
            int idx = r * NM + c;
            sY[idx] *= invn;
            sZ[idx] = (r == c) ? 1.f : 0.f;
        }
    __syncthreads();

    for (int it = 0; it < NSI; it++) {
        // T = 0.5*(3I - Z@Y)
        float t0x = 0.f, t0y = 0.f, t0z = 0.f, t0w = 0.f;
        float t1x = 0.f, t1y = 0.f, t1z = 0.f, t1w = 0.f;
#pragma unroll 8
        for (int k = 0; k < NM; k++) {
            float a0 = sZ[(r0 + 0) * NM + k];
            float a1 = sZ[(r0 + 1) * NM + k];
            float4 bv = *reinterpret_cast<const float4*>(&sY[k * NM + c0]);
            t0x += a0 * bv.x; t0y += a0 * bv.y; t0z += a0 * bv.z; t0w += a0 * bv.w;
            t1x += a1 * bv.x; t1y += a1 * bv.y; t1z += a1 * bv.z; t1w += a1 * bv.w;
        }
        {
            int r = r0, c = c0;
            sT[r * NM + c + 0] = ((r == c + 0) ? 1.5f : 0.f) - 0.5f * t0x;
            sT[r * NM + c + 1] = ((r == c + 1) ? 1.5f : 0.f) - 0.5f * t0y;
            sT[r * NM + c + 2] = ((r == c + 2) ? 1.5f : 0.f) - 0.5f * t0z;
            sT[r * NM + c + 3] = ((r == c + 3) ? 1.5f : 0.f) - 0.5f * t0w;
            r = r0 + 1;
            sT[r * NM + c + 0] = ((r == c + 0) ? 1.5f : 0.f) - 0.5f * t1x;
            sT[r * NM + c + 1] = ((r == c + 1) ? 1.5f : 0.f) - 0.5f * t1y;
            sT[r * NM + c + 2] = ((r == c + 2) ? 1.5f : 0.f) - 0.5f * t1z;
            sT[r * NM + c + 3] = ((r == c + 3) ? 1.5f : 0.f) - 0.5f * t1w;
        }
        __syncthreads();

        // Ynew = Y@T ; Znew = T@Z (both into registers, then write back)
        float y0[4] = {0.f,0.f,0.f,0.f}, y1[4] = {0.f,0.f,0.f,0.f};
        float z0[4] = {0.f,0.f,0.f,0.f}, z1[4] = {0.f,0.f,0.f,0.f};
#pragma unroll 4
        for (int k = 0; k < NM; k++) {
            float ay0 = sY[(r0 + 0) * NM + k];
            float ay1 = sY[(r0 + 1) * NM + k];
            float4 bt = *reinterpret_cast<const float4*>(&sT[k * NM + c0]);
            y0[0] += ay0 * bt.x; y0[1] += ay0 * bt.y; y0[2] += ay0 * bt.z; y0[3] += ay0 * bt.w;
            y1[0] += ay1 * bt.x; y1[1] += ay1 * bt.y; y1[2] += ay1 * bt.z; y1[3] += ay1 * bt.w;
            float at0 = sT[(r0 + 0) * NM + k];
            float at1 = sT[(r0 + 1) * NM + k];
            float4 bz = *reinterpret_cast<const float4*>(&sZ[k * NM + c0]);
            z0[0] += at0 * bz.x; z0[1] += at0 * bz.y; z0[2] += at0 * bz.z; z0[3] += at0 * bz.w;
            z1[0] += at1 * bz.x; z1[1] += at1 * bz.y; z1[2] += at1 * bz.z; z1[3] += at1 * bz.w;
        }
        __syncthreads();          // all reads of sY/sZ done
#pragma unroll
        for (int j = 0; j < 4; j++) {
            sY[(r0 + 0) * NM + c0 + j] = y0[j];
            sY[(r0 + 1) * NM + c0 + j] = y1[j];
            sZ[(r0 + 0) * NM + c0 + j] = z0[j];
            sZ[(r0 + 1) * NM + c0 + j] = z1[j];
        }
        __syncthreads();
    }

    // w==0 (content cov): need A^{-1/2} = Z / sqrt(norm)
    // w==1 (style cov):   need A^{ 1/2} = Y * sqrt(norm)
    const float sq_n  = sqrtf(norm);
    const float scale = (w == 0) ? (1.f / sq_n) : sq_n;
    const float* __restrict__ src = (w == 0) ? sZ : sY;
    float* __restrict__ dst = g_ns[w][b];
#pragma unroll
    for (int i = 0; i < 2; i++)
#pragma unroll
        for (int j = 0; j < 4; j++) {
            int idx = (r0 + i) * NM + c0 + j;
            dst[idx] = src[idx] * scale;
        }
}

// ---------------------------------------------------------------------------
// K3: M = cov_b_sqrt @ cov_c_invsqrt ; v = mu_B - M*mu_A. grid = 64, block = 256.
// ---------------------------------------------------------------------------
__global__ __launch_bounds__(256)
void k_mix()
{
    const int b = blockIdx.x;
    __shared__ __align__(16) float sA[NM * NM];
    __shared__ __align__(16) float sB[NM * NM];
    __shared__ __align__(16) float sC[NM * NM];
    const int tid = threadIdx.x;
    const int tx = tid & 15, ty = tid >> 4;
    const int ry = ty * 4, rx = tx * 4;

#pragma unroll
    for (int l = 0; l < 4; l++) {
        int idx4 = (tid + l * 256) * 4;
        *reinterpret_cast<float4*>(&sA[idx4]) =
            *reinterpret_cast<const float4*>(&g_ns[1][b][idx4]);
        *reinterpret_cast<float4*>(&sB[idx4]) =
            *reinterpret_cast<const float4*>(&g_ns[0][b][idx4]);
    }
    __syncthreads();

    float acc[4][4];
#pragma unroll
    for (int i = 0; i < 4; i++)
#pragma unroll
        for (int j = 0; j < 4; j++) acc[i][j] = 0.f;

#pragma unroll 4
    for (int k = 0; k < NM; k++) {
        float a0 = sA[(ry + 0) * NM + k], a1 = sA[(ry + 1) * NM + k];
        float a2 = sA[(ry + 2) * NM + k], a3 = sA[(ry + 3) * NM + k];
        float4 bv = *reinterpret_cast<const float4*>(&sB[k * NM + rx]);
        acc[0][0] += a0 * bv.x; acc[0][1] += a0 * bv.y; acc[0][2] += a0 * bv.z; acc[0][3] += a0 * bv.w;
        acc[1][0] += a1 * bv.x; acc[1][1] += a1 * bv.y; acc[1][2] += a1 * bv.z; acc[1][3] += a1 * bv.w;
        acc[2][0] += a2 * bv.x; acc[2][1] += a2 * bv.y; acc[2][2] += a2 * bv.z; acc[2][3] += a2 * bv.w;
        acc[3][0] += a3 * bv.x; acc[3][1] += a3 * bv.y; acc[3][2] += a3 * bv.z; acc[3][3] += a3 * bv.w;
    }
#pragma unroll
    for (int i = 0; i < 4; i++)
#pragma unroll
        for (int j = 0; j < 4; j++) {
            int idx = (ry + i) * NM + rx + j;
            g_M[b][idx] = acc[i][j];
            sC[idx]     = acc[i][j];
        }
    __syncthreads();

    if (tid < NM) {
        float mv = g_mean[1][b][tid];
#pragma unroll 8
        for (int k = 0; k < NM; k++) mv -= sC[tid * NM + k] * g_mean[0][b][k];
        g_v[b][tid] = mv;
    }
}

// ---------------------------------------------------------------------------
// K4: out = alpha*(M @ c_A + v) + (1-alpha)*c_A.
// grid = NB*16 (16 s-tiles of 256 per batch), block = 256.
// ---------------------------------------------------------------------------
__global__ __launch_bounds__(256)
void k_out(const float* __restrict__ cA, const float* __restrict__ alphap,
           float* __restrict__ outp)
{
    const int b  = blockIdx.x >> 4;
    const int s0 = (blockIdx.x & 15) * 256;

    __shared__ __align__(16) float sM[NM * NM];
    __shared__ __align__(16) float xt[NM * 64];

    const int tid = threadIdx.x;
    const int tx = tid & 15, ty = tid >> 4;
    const int ry = ty * 4, rx = tx * 4;

    const float alpha = __ldg(alphap);
    const float beta  = 1.f - alpha;
    const float* __restrict__ X = cA  + (size_t)b * NM * HW;
    float* __restrict__ O       = outp + (size_t)b * NM * HW;

#pragma unroll
    for (int l = 0; l < 4; l++) {
        int idx4 = (tid + l * 256) * 4;
        *reinterpret_cast<float4*>(&sM[idx4]) =
            *reinterpret_cast<const float4*>(&g_M[b][idx4]);
    }
    float vr[4];
#pragma unroll
    for (int i = 0; i < 4; i++) vr[i] = g_v[b][ry + i];

    for (int sc = 0; sc < 4; sc++) {
        __syncthreads();   // tile consumed (also covers sM load on sc==0)
#pragma unroll
        for (int l = 0; l < 4; l++) {
            int idx = tid + l * 256;
            int r   = idx >> 4;
            int c4  = (idx & 15) * 4;
            *reinterpret_cast<float4*>(&xt[r * 64 + c4]) =
                *reinterpret_cast<const float4*>(&X[(size_t)r * HW + s0 + sc * 64 + c4]);
        }
        __syncthreads();

        float acc[4][4];
#pragma unroll
        for (int i = 0; i < 4; i++)
#pragma unroll
            for (int j = 0; j < 4; j++) acc[i][j] = 0.f;

#pragma unroll 4
        for (int k = 0; k < NM; k++) {
            float a0 = sM[(ry + 0) * NM + k], a1 = sM[(ry + 1) * NM + k];
            float a2 = sM[(ry + 2) * NM + k], a3 = sM[(ry + 3) * NM + k];
            float4 bv = *reinterpret_cast<const float4*>(&xt[k * 64 + rx]);
            acc[0][0] += a0 * bv.x; acc[0][1] += a0 * bv.y; acc[0][2] += a0 * bv.z; acc[0][3] += a0 * bv.w;
            acc[1][0] += a1 * bv.x; acc[1][1] += a1 * bv.y; acc[1][2] += a1 * bv.z; acc[1][3] += a1 * bv.w;
            acc[2][0] += a2 * bv.x; acc[2][1] += a2 * bv.y; acc[2][2] += a2 * bv.z; acc[2][3] += a2 * bv.w;
            acc[3][0] += a3 * bv.x; acc[3][1] += a3 * bv.y; acc[3][2] += a3 * bv.z; acc[3][3] += a3 * bv.w;
        }

#pragma unroll
        for (int i = 0; i < 4; i++) {
            float4 cv = *reinterpret_cast<const float4*>(&xt[(ry + i) * 64 + rx]);
            float4 o;
            o.x = alpha * (acc[i][0] + vr[i]) + beta * cv.x;
            o.y = alpha * (acc[i][1] + vr[i]) + beta * cv.y;
            o.z = alpha * (acc[i][2] + vr[i]) + beta * cv.z;
            o.w = alpha * (acc[i][3] + vr[i]) + beta * cv.w;
            *reinterpret_cast<float4*>(&O[(size_t)(ry + i) * HW + s0 + sc * 64 + rx]) = o;
        }
    }
}

// ---------------------------------------------------------------------------
extern "C" void kernel_launch(void* const* d_in, const int* in_sizes, int n_in,
                              void* d_out, int out_size)
{
    const float* cA    = (const float*)d_in[0];
    const float* sB    = (const float*)d_in[1];
    const float* alpha = (const float*)d_in[2];
    float* out         = (float*)d_out;

    k_gram<<<KSPLIT * 128, 256>>>(cA, sB);
    k_ns  <<<128, 512>>>();
    k_mix <<<NB, 256>>>();
    k_out <<<NB * 16, 256>>>(cA, alpha, out);
}

// round 7
// speedup vs baseline: 1.1984x; 1.1984x over previous
#include <cuda_runtime.h>

// ---------------------------------------------------------------------------
// WCT: whitening-coloring transform.
//   B=8, C=512, H=W=64, G=8  ->  NB = 64 batches, each [NM=64, HW=4096] fp32.
// K1 k_gram: partial Grams (split-k x8) + partial row sums (c_A and s_B)
// K2 k_ns  : cov assembly + coupled Newton-Schulz x10 (symmetric-read float4)
// K3 k_mix : Mt = (cov_b_sqrt @ cov_c_invsqrt)^T ; v = mu_B - M*mu_A
// K4 k_out : out = alpha*(M @ c_A + v) + (1-alpha)*c_A
// ---------------------------------------------------------------------------

#define NM 64
#define HW 4096
#define NB 64
#define KSPLIT 8
#define KCHUNK (HW / KSPLIT)   // 512
#define NSI 10
#define EPSV 1e-5f
#define TS 68                  // padded tile stride for k_gram (along-k float4)

__device__ __align__(16) float g_gram[KSPLIT][2][NB][NM * NM]; // 16 MB
__device__ __align__(16) float g_rows[KSPLIT][2][NB][NM];
__device__ __align__(16) float g_mean[2][NB][NM];
__device__ __align__(16) float g_ns[2][NB][NM * NM];
__device__ __align__(16) float g_Mt[NB][NM * NM];              // M transposed
__device__ __align__(16) float g_v[NB][NM];

// 16 FMAs: acc[i][j] += av[i] * bv[j]
#define OUTER16(acc, av, bv)                                                  \
    acc[0][0] += av.x * bv.x; acc[0][1] += av.x * bv.y;                       \
    acc[0][2] += av.x * bv.z; acc[0][3] += av.x * bv.w;                       \
    acc[1][0] += av.y * bv.x; acc[1][1] += av.y * bv.y;                       \
    acc[1][2] += av.y * bv.z; acc[1][3] += av.y * bv.w;                       \
    acc[2][0] += av.z * bv.x; acc[2][1] += av.z * bv.y;                       \
    acc[2][2] += av.z * bv.z; acc[2][3] += av.z * bv.w;                       \
    acc[3][0] += av.w * bv.x; acc[3][1] += av.w * bv.y;                       \
    acc[3][2] += av.w * bv.z; acc[3][3] += av.w * bv.w;

// dot of two float4 accumulated into scalar (4 FFMA)
#define DOT4(ACC, A, B)                                                       \
    ACC += A.x * B.x; ACC += A.y * B.y; ACC += A.z * B.z; ACC += A.w * B.w;

// ---------------------------------------------------------------------------
// K1: partial Gram + row sums. grid = KSPLIT*128, block = 256.
// Tile t[row][k] stride 68; compute vectorized ALONG K (unroll-4):
//   per 4k: 8 x LDS.128 + 64 FFMA. Output cols interleaved {tx,tx+16,+32,+48}
//   so the 16 b-side float4 chunks are 2-way (= 256B crossbar floor).
// Register-prefetch double buffering hides LDG.
// ---------------------------------------------------------------------------
__global__ __launch_bounds__(256)
void k_gram(const float* __restrict__ cAp, const float* __restrict__ sBp)
{
    const int pair  = blockIdx.x & 127;
    const int chunk = blockIdx.x >> 7;
    const int which = pair >> 6;
    const int b     = pair & 63;
    const float* __restrict__ X =
        (which ? sBp : cAp) + (size_t)b * NM * HW + chunk * KCHUNK;

    __shared__ __align__(16) float t[NM * TS];

    const int tid = threadIdx.x;
    const int tx = tid & 15, ty = tid >> 4;
    const int ry = ty * 4;

    float acc[4][4];
#pragma unroll
    for (int i = 0; i < 4; i++)
#pragma unroll
        for (int j = 0; j < 4; j++) acc[i][j] = 0.f;
    float rowAcc = 0.f;

    // prefetch tile 0
    float4 pf[4];
#pragma unroll
    for (int l = 0; l < 4; l++)
        pf[l] = *reinterpret_cast<const float4*>(
            X + (size_t)(ty + 16 * l) * HW + 4 * tx);

    for (int kt = 0; kt < KCHUNK; kt += 64) {
        __syncthreads();   // previous tile fully consumed
#pragma unroll
        for (int l = 0; l < 4; l++)
            *reinterpret_cast<float4*>(&t[(ty + 16 * l) * TS + 4 * tx]) = pf[l];
        if (kt + 64 < KCHUNK) {
#pragma unroll
            for (int l = 0; l < 4; l++)
                pf[l] = *reinterpret_cast<const float4*>(
                    X + (size_t)(ty + 16 * l) * HW + kt + 64 + 4 * tx);
        }
        __syncthreads();

#pragma unroll 2
        for (int k = 0; k < 64; k += 4) {
            float4 a0 = *reinterpret_cast<const float4*>(&t[(ry + 0) * TS + k]);
            float4 a1 = *reinterpret_cast<const float4*>(&t[(ry + 1) * TS + k]);
            float4 a2 = *reinterpret_cast<const float4*>(&t[(ry + 2) * TS + k]);
            float4 a3 = *reinterpret_cast<const float4*>(&t[(ry + 3) * TS + k]);
            float4 b0 = *reinterpret_cast<const float4*>(&t[(tx +  0) * TS + k]);
            float4 b1 = *reinterpret_cast<const float4*>(&t[(tx + 16) * TS + k]);
            float4 b2 = *reinterpret_cast<const float4*>(&t[(tx + 32) * TS + k]);
            float4 b3 = *reinterpret_cast<const float4*>(&t[(tx + 48) * TS + k]);
            DOT4(acc[0][0], a0, b0); DOT4(acc[0][1], a0, b1);
            DOT4(acc[0][2], a0, b2); DOT4(acc[0][3], a0, b3);
            DOT4(acc[1][0], a1, b0); DOT4(acc[1][1], a1, b1);
            DOT4(acc[1][2], a1, b2); DOT4(acc[1][3], a1, b3);
            DOT4(acc[2][0], a2, b0); DOT4(acc[2][1], a2, b1);
            DOT4(acc[2][2], a2, b2); DOT4(acc[2][3], a2, b3);
            DOT4(acc[3][0], a3, b0); DOT4(acc[3][1], a3, b1);
            DOT4(acc[3][2], a3, b2); DOT4(acc[3][3], a3, b3);
        }
        if (tid < 64) {
            float s = 0.f;
#pragma unroll 4
            for (int c = 0; c < 64; c += 4) {
                float4 v = *reinterpret_cast<const float4*>(&t[tid * TS + c]);
                s += v.x + v.y + v.z + v.w;
            }
            rowAcc += s;
        }
    }

    float* __restrict__ go = g_gram[chunk][which][b];
#pragma unroll
    for (int i = 0; i < 4; i++)
#pragma unroll
        for (int j = 0; j < 4; j++)
            go[(ry + i) * NM + tx + 16 * j] = acc[i][j];
    if (tid < 64) g_rows[chunk][which][b][tid] = rowAcc;
}

// ---------------------------------------------------------------------------
// K2: cov assembly + coupled Newton-Schulz. grid = 128, block = 256.
// All of Y, Z, T are symmetric (polynomials of the same SPD matrix), so the
// row-indexed operand is read as a column float4: per k, 2 LDS.128 + 16 FFMA.
// Iter 0: Z=I so T = 1.5I - 0.5Y and Z1 = T (bitwise equal to the matmuls).
// Last iter: only the needed factor (w=0 -> Z, w=1 -> Y) is updated.
// ---------------------------------------------------------------------------
__global__ __launch_bounds__(256)
void k_ns()
{
    const int w = blockIdx.x >> 6;
    const int b = blockIdx.x & 63;

    __shared__ __align__(16) float sY[NM * NM];
    __shared__ __align__(16) float sZ[NM * NM];
    __shared__ __align__(16) float sT[NM * NM];

    const int tid = threadIdx.x;
    const int tx = tid & 15, ty = tid >> 4;
    const int ry = ty * 4, cx = tx * 4;

    // means into sT[0..63] (temp) and global
    if (tid < NM) {
        float s = 0.f;
#pragma unroll
        for (int ch = 0; ch < KSPLIT; ch++) s += g_rows[ch][w][b][tid];
        float m = s * (1.f / (float)HW);
        sT[tid] = m;
        g_mean[w][b][tid] = m;
    }
    __syncthreads();

    // cov -> sY, accumulate Frobenius^2
    float sq = 0.f;
#pragma unroll
    for (int i = 0; i < 4; i++) {
        float mr = sT[ry + i];
#pragma unroll
        for (int j = 0; j < 4; j++) {
            int r = ry + i, c = cx + j;
            int idx = r * NM + c;
            float g = 0.f;
#pragma unroll
            for (int ch = 0; ch < KSPLIT; ch++) g += g_gram[ch][w][b][idx];
            float cv = (g - (float)HW * mr * sT[c]) * (1.f / (float)(HW - 1));
            if (r == c) cv += EPSV;
            sY[idx] = cv;
            sq += cv * cv;
        }
    }
    __syncthreads();              // means consumed
    sT[tid] = sq;
    __syncthreads();
#pragma unroll
    for (int s = 128; s > 0; s >>= 1) {
        if (tid < s) sT[tid] += sT[tid + s];
        __syncthreads();
    }
    const float norm = sqrtf(sT[0]);
    const float invn = 1.f / norm;
    __syncthreads();

    // Y = A/norm (Z = I handled by iter-0 shortcut)
#pragma unroll
    for (int i = 0; i < 4; i++)
#pragma unroll
        for (int j = 0; j < 4; j++)
            sY[(ry + i) * NM + cx + j] *= invn;
    __syncthreads();

    // ---- iteration 0: T = 1.5I - 0.5*Y ; Ynew = Y@T ; Z1 = T ----
#pragma unroll
    for (int i = 0; i < 4; i++)
#pragma unroll
        for (int j = 0; j < 4; j++) {
            int r = ry + i, c = cx + j;
            sT[r * NM + c] = ((r == c) ? 1.5f : 0.f) - 0.5f * sY[r * NM + c];
        }
    __syncthreads();
    {
        float ya[4][4];
#pragma unroll
        for (int i = 0; i < 4; i++)
#pragma unroll
            for (int j = 0; j < 4; j++) ya[i][j] = 0.f;
#pragma unroll 4
        for (int k = 0; k < NM; k++) {
            float4 av = *reinterpret_cast<const float4*>(&sY[k * NM + ry]); // Y sym
            float4 bv = *reinterpret_cast<const float4*>(&sT[k * NM + cx]);
            OUTER16(ya, av, bv);
        }
        __syncthreads();
#pragma unroll
        for (int i = 0; i < 4; i++)
#pragma unroll
            for (int j = 0; j < 4; j++) {
                int idx = (ry + i) * NM + cx + j;
                sY[idx] = ya[i][j];
                sZ[idx] = sT[idx];
            }
        __syncthreads();
    }

    // ---- iterations 1..9 ----
    for (int it = 1; it < NSI; it++) {
        // T = 1.5I - 0.5*Z@Y
        float ta[4][4];
#pragma unroll
        for (int i = 0; i < 4; i++)
#pragma unroll
            for (int j = 0; j < 4; j++) ta[i][j] = 0.f;
#pragma unroll 4
        for (int k = 0; k < NM; k++) {
            float4 av = *reinterpret_cast<const float4*>(&sZ[k * NM + ry]); // Z sym
            float4 bv = *reinterpret_cast<const float4*>(&sY[k * NM + cx]);
            OUTER16(ta, av, bv);
        }
#pragma unroll
        for (int i = 0; i < 4; i++)
#pragma unroll
            for (int j = 0; j < 4; j++) {
                int r = ry + i, c = cx + j;
                sT[r * NM + c] = ((r == c) ? 1.5f : 0.f) - 0.5f * ta[i][j];
            }
        __syncthreads();

        if (it < NSI - 1) {
            // Ynew = Y@T ; Znew = T@Z (combined)
            float ya[4][4], za[4][4];
#pragma unroll
            for (int i = 0; i < 4; i++)
#pragma unroll
                for (int j = 0; j < 4; j++) { ya[i][j] = 0.f; za[i][j] = 0.f; }
#pragma unroll 4
            for (int k = 0; k < NM; k++) {
                float4 ay = *reinterpret_cast<const float4*>(&sY[k * NM + ry]);
                float4 bt = *reinterpret_cast<const float4*>(&sT[k * NM + cx]);
                OUTER16(ya, ay, bt);
                float4 at = *reinterpret_cast<const float4*>(&sT[k * NM + ry]);
                float4 bz = *reinterpret_cast<const float4*>(&sZ[k * NM + cx]);
                OUTER16(za, at, bz);
            }
            __syncthreads();
#pragma unroll
            for (int i = 0; i < 4; i++)
#pragma unroll
                for (int j = 0; j < 4; j++) {
                    int idx = (ry + i) * NM + cx + j;
                    sY[idx] = ya[i][j];
                    sZ[idx] = za[i][j];
                }
            __syncthreads();
        } else if (w == 1) {
            // only Y needed
            float ya[4][4];
#pragma unroll
            for (int i = 0; i < 4; i++)
#pragma unroll
                for (int j = 0; j < 4; j++) ya[i][j] = 0.f;
#pragma unroll 4
            for (int k = 0; k < NM; k++) {
                float4 ay = *reinterpret_cast<const float4*>(&sY[k * NM + ry]);
                float4 bt = *reinterpret_cast<const float4*>(&sT[k * NM + cx]);
                OUTER16(ya, ay, bt);
            }
            __syncthreads();
#pragma unroll
            for (int i = 0; i < 4; i++)
#pragma unroll
                for (int j = 0; j < 4; j++)
                    sY[(ry + i) * NM + cx + j] = ya[i][j];
            __syncthreads();
        } else {
            // only Z needed
            float za[4][4];
#pragma unroll
            for (int i = 0; i < 4; i++)
#pragma unroll
                for (int j = 0; j < 4; j++) za[i][j] = 0.f;
#pragma unroll 4
            for (int k = 0; k < NM; k++) {
                float4 at = *reinterpret_cast<const float4*>(&sT[k * NM + ry]);
                float4 bz = *reinterpret_cast<const float4*>(&sZ[k * NM + cx]);
                OUTER16(za, at, bz);
            }
            __syncthreads();
#pragma unroll
            for (int i = 0; i < 4; i++)
#pragma unroll
                for (int j = 0; j < 4; j++)
                    sZ[(ry + i) * NM + cx + j] = za[i][j];
            __syncthreads();
        }
    }

    const float sq_n  = sqrtf(norm);
    const float scale = (w == 0) ? (1.f / sq_n) : sq_n;
    const float* __restrict__ src = (w == 0) ? sZ : sY;
    float* __restrict__ dst = g_ns[w][b];
#pragma unroll
    for (int i = 0; i < 4; i++)
#pragma unroll
        for (int j = 0; j < 4; j++) {
            int idx = (ry + i) * NM + cx + j;
            dst[idx] = src[idx] * scale;
        }
}

// ---------------------------------------------------------------------------
// K3: Mt = (cov_b_sqrt @ cov_c_invsqrt)^T ; v = mu_B - M*mu_A. grid=64, blk=256.
// Both factors symmetric -> a-side read as column float4.
// ---------------------------------------------------------------------------
__global__ __launch_bounds__(256)
void k_mix()
{
    const int b = blockIdx.x;
    __shared__ __align__(16) float sA[NM * NM];
    __shared__ __align__(16) float sB[NM * NM];
    __shared__ __align__(16) float sCt[NM * NM];
    const int tid = threadIdx.x;
    const int tx = tid & 15, ty = tid >> 4;
    const int ry = ty * 4, cx = tx * 4;

#pragma unroll
    for (int l = 0; l < 4; l++) {
        int idx4 = (tid + l * 256) * 4;
        *reinterpret_cast<float4*>(&sA[idx4]) =
            *reinterpret_cast<const float4*>(&g_ns[1][b][idx4]);
        *reinterpret_cast<float4*>(&sB[idx4]) =
            *reinterpret_cast<const float4*>(&g_ns[0][b][idx4]);
    }
    __syncthreads();

    float acc[4][4];
#pragma unroll
    for (int i = 0; i < 4; i++)
#pragma unroll
        for (int j = 0; j < 4; j++) acc[i][j] = 0.f;

#pragma unroll 4
    for (int k = 0; k < NM; k++) {
        float4 av = *reinterpret_cast<const float4*>(&sA[k * NM + ry]); // A sym
        float4 bv = *reinterpret_cast<const float4*>(&sB[k * NM + cx]);
        OUTER16(acc, av, bv);
    }
#pragma unroll
    for (int i = 0; i < 4; i++)
#pragma unroll
        for (int j = 0; j < 4; j++) {
            int tidx = (cx + j) * NM + (ry + i);   // transposed
            sCt[tidx]      = acc[i][j];
            g_Mt[b][tidx]  = acc[i][j];
        }
    __syncthreads();

    if (tid < NM) {
        float mv = g_mean[1][b][tid];
#pragma unroll 8
        for (int k = 0; k < NM; k++)
            mv -= sCt[k * NM + tid] * g_mean[0][b][k];   // M[tid][k]
        g_v[b][tid] = mv;
    }
}

// ---------------------------------------------------------------------------
// K4: out = alpha*(M @ c_A + v) + (1-alpha)*c_A. grid = NB*16, block = 256.
// a = Mt column float4, b = X tile column float4: per k, 2 LDS.128 + 16 FFMA.
// Register-prefetched X tiles.
// ---------------------------------------------------------------------------
__global__ __launch_bounds__(256)
void k_out(const float* __restrict__ cAp, const float* __restrict__ alphap,
           float* __restrict__ outp)
{
    const int b  = blockIdx.x >> 4;
    const int s0 = (blockIdx.x & 15) * 256;

    __shared__ __align__(16) float sMt[NM * NM];
    __shared__ __align__(16) float xt[NM * NM];

    const int tid = threadIdx.x;
    const int tx = tid & 15, ty = tid >> 4;
    const int ry = ty * 4, sx = tx * 4;

    const float alpha = __ldg(alphap);
    const float beta  = 1.f - alpha;
    const float* __restrict__ X = cAp  + (size_t)b * NM * HW + s0;
    float* __restrict__ O       = outp + (size_t)b * NM * HW + s0;

#pragma unroll
    for (int l = 0; l < 4; l++) {
        int idx4 = (tid + l * 256) * 4;
        *reinterpret_cast<float4*>(&sMt[idx4]) =
            *reinterpret_cast<const float4*>(&g_Mt[b][idx4]);
    }
    float vr[4];
#pragma unroll
    for (int i = 0; i < 4; i++) vr[i] = g_v[b][ry + i];

    // prefetch tile 0
    float4 pf[4];
#pragma unroll
    for (int l = 0; l < 4; l++)
        pf[l] = *reinterpret_cast<const float4*>(
            X + (size_t)(ty + 16 * l) * HW + 4 * tx);

    for (int sc = 0; sc < 4; sc++) {
        __syncthreads();   // previous tile consumed (covers sMt load on sc==0)
#pragma unroll
        for (int l = 0; l < 4; l++)
            *reinterpret_cast<float4*>(&xt[(ty + 16 * l) * NM + 4 * tx]) = pf[l];
        if (sc < 3) {
#pragma unroll
            for (int l = 0; l < 4; l++)
                pf[l] = *reinterpret_cast<const float4*>(
                    X + (size_t)(ty + 16 * l) * HW + (sc + 1) * 64 + 4 * tx);
        }
        __syncthreads();

        float acc[4][4];
#pragma unroll
        for (int i = 0; i < 4; i++)
#pragma unroll
            for (int j = 0; j < 4; j++) acc[i][j] = 0.f;

#pragma unroll 8
        for (int k = 0; k < NM; k++) {
            float4 av = *reinterpret_cast<const float4*>(&sMt[k * NM + ry]);
            float4 bv = *reinterpret_cast<const float4*>(&xt[k * NM + sx]);
            OUTER16(acc, av, bv);
        }

#pragma unroll
        for (int i = 0; i < 4; i++) {
            float4 cv = *reinterpret_cast<const float4*>(&xt[(ry + i) * NM + sx]);
            float4 o;
            o.x = alpha * (acc[i][0] + vr[i]) + beta * cv.x;
            o.y = alpha * (acc[i][1] + vr[i]) + beta * cv.y;
            o.z = alpha * (acc[i][2] + vr[i]) + beta * cv.z;
            o.w = alpha * (acc[i][3] + vr[i]) + beta * cv.w;
            *reinterpret_cast<float4*>(
                &O[(size_t)(ry + i) * HW + sc * 64 + sx]) = o;
        }
    }
}

// ---------------------------------------------------------------------------
extern "C" void kernel_launch(void* const* d_in, const int* in_sizes, int n_in,
                              void* d_out, int out_size)
{
    const float* cA    = (const float*)d_in[0];
    const float* sB    = (const float*)d_in[1];
    const float* alpha = (const float*)d_in[2];
    float* out         = (float*)d_out;

    k_gram<<<KSPLIT * 128, 256>>>(cA, sB);
    k_ns  <<<128, 256>>>();
    k_mix <<<NB, 256>>>();
    k_out <<<NB * 16, 256>>>(cA, alpha, out);
}

// round 8
// speedup vs baseline: 1.2009x; 1.0021x over previous
#include <cuda_runtime.h>

// ---------------------------------------------------------------------------
// WCT: whitening-coloring transform.
//   B=8, C=512, H=W=64, G=8  ->  NB = 64 batches, each [NM=64, HW=4096] fp32.
// K1 k_gram: partial Grams (split-k x8) + partial row sums (c_A and s_B)
// K2 k_ns  : cov assembly + coupled Newton-Schulz x10 (symmetric-read float4)
// K3 k_mix : Mt = (cov_b_sqrt @ cov_c_invsqrt)^T ; v = mu_B - M*mu_A
// K4 k_out : out = alpha*(M @ c_A + v) + (1-alpha)*c_A
// ---------------------------------------------------------------------------

#define NM 64
#define HW 4096
#define NB 64
#define KSPLIT 8
#define KCHUNK (HW / KSPLIT)   // 512
#define NSI 10
#define EPSV 1e-5f
#define TS 68                  // padded tile stride for k_gram (along-k float4)

__device__ __align__(16) float g_gram[KSPLIT][2][NB][NM * NM]; // 16 MB
__device__ __align__(16) float g_rows[KSPLIT][2][NB][NM];
__device__ __align__(16) float g_mean[2][NB][NM];
__device__ __align__(16) float g_ns[2][NB][NM * NM];
__device__ __align__(16) float g_Mt[NB][NM * NM];              // M transposed
__device__ __align__(16) float g_v[NB][NM];

// 16 FMAs: acc[i][j] += av[i] * bv[j]
#define OUTER16(acc, av, bv)                                                  \
    acc[0][0] += av.x * bv.x; acc[0][1] += av.x * bv.y;                       \
    acc[0][2] += av.x * bv.z; acc[0][3] += av.x * bv.w;                       \
    acc[1][0] += av.y * bv.x; acc[1][1] += av.y * bv.y;                       \
    acc[1][2] += av.y * bv.z; acc[1][3] += av.y * bv.w;                       \
    acc[2][0] += av.z * bv.x; acc[2][1] += av.z * bv.y;                       \
    acc[2][2] += av.z * bv.z; acc[2][3] += av.z * bv.w;                       \
    acc[3][0] += av.w * bv.x; acc[3][1] += av.w * bv.y;                       \
    acc[3][2] += av.w * bv.z; acc[3][3] += av.w * bv.w;

// dot of two float4 accumulated into scalar (4 FFMA)
#define DOT4(ACC, A, B)                                                       \
    ACC += A.x * B.x; ACC += A.y * B.y; ACC += A.z * B.z; ACC += A.w * B.w;

// ---------------------------------------------------------------------------
// K1: partial Gram + row sums. grid = KSPLIT*128, block = 256.
// Tile t[row][k] stride 68; compute vectorized ALONG K (unroll-4):
//   per 4k: 8 x LDS.128 + 64 FFMA. Output cols interleaved {tx,tx+16,+32,+48}
//   so the 16 b-side float4 chunks are 2-way (= 256B crossbar floor).
// Register-prefetch double buffering hides LDG.
// ---------------------------------------------------------------------------
__global__ __launch_bounds__(256)
void k_gram(const float* __restrict__ cAp, const float* __restrict__ sBp)
{
    const int pair  = blockIdx.x & 127;
    const int chunk = blockIdx.x >> 7;
    const int which = pair >> 6;
    const int b     = pair & 63;
    const float* __restrict__ X =
        (which ? sBp : cAp) + (size_t)b * NM * HW + chunk * KCHUNK;

    __shared__ __align__(16) float t[NM * TS];

    const int tid = threadIdx.x;
    const int tx = tid & 15, ty = tid >> 4;
    const int ry = ty * 4;

    float acc[4][4];
#pragma unroll
    for (int i = 0; i < 4; i++)
#pragma unroll
        for (int j = 0; j < 4; j++) acc[i][j] = 0.f;
    float rowAcc = 0.f;

    // prefetch tile 0
    float4 pf[4];
#pragma unroll
    for (int l = 0; l < 4; l++)
        pf[l] = *reinterpret_cast<const float4*>(
            X + (size_t)(ty + 16 * l) * HW + 4 * tx);

    for (int kt = 0; kt < KCHUNK; kt += 64) {
        __syncthreads();   // previous tile fully consumed
#pragma unroll
        for (int l = 0; l < 4; l++)
            *reinterpret_cast<float4*>(&t[(ty + 16 * l) * TS + 4 * tx]) = pf[l];
        if (kt + 64 < KCHUNK) {
#pragma unroll
            for (int l = 0; l < 4; l++)
                pf[l] = *reinterpret_cast<const float4*>(
                    X + (size_t)(ty + 16 * l) * HW + kt + 64 + 4 * tx);
        }
        __syncthreads();

#pragma unroll 2
        for (int k = 0; k < 64; k += 4) {
            float4 a0 = *reinterpret_cast<const float4*>(&t[(ry + 0) * TS + k]);
            float4 a1 = *reinterpret_cast<const float4*>(&t[(ry + 1) * TS + k]);
            float4 a2 = *reinterpret_cast<const float4*>(&t[(ry + 2) * TS + k]);
            float4 a3 = *reinterpret_cast<const float4*>(&t[(ry + 3) * TS + k]);
            float4 b0 = *reinterpret_cast<const float4*>(&t[(tx +  0) * TS + k]);
            float4 b1 = *reinterpret_cast<const float4*>(&t[(tx + 16) * TS + k]);
            float4 b2 = *reinterpret_cast<const float4*>(&t[(tx + 32) * TS + k]);
            float4 b3 = *reinterpret_cast<const float4*>(&t[(tx + 48) * TS + k]);
            DOT4(acc[0][0], a0, b0); DOT4(acc[0][1], a0, b1);
            DOT4(acc[0][2], a0, b2); DOT4(acc[0][3], a0, b3);
            DOT4(acc[1][0], a1, b0); DOT4(acc[1][1], a1, b1);
            DOT4(acc[1][2], a1, b2); DOT4(acc[1][3], a1, b3);
            DOT4(acc[2][0], a2, b0); DOT4(acc[2][1], a2, b1);
            DOT4(acc[2][2], a2, b2); DOT4(acc[2][3], a2, b3);
            DOT4(acc[3][0], a3, b0); DOT4(acc[3][1], a3, b1);
            DOT4(acc[3][2], a3, b2); DOT4(acc[3][3], a3, b3);
        }
        if (tid < 64) {
            float s = 0.f;
#pragma unroll 4
            for (int c = 0; c < 64; c += 4) {
                float4 v = *reinterpret_cast<const float4*>(&t[tid * TS + c]);
                s += v.x + v.y + v.z + v.w;
            }
            rowAcc += s;
        }
    }

    float* __restrict__ go = g_gram[chunk][which][b];
#pragma unroll
    for (int i = 0; i < 4; i++)
#pragma unroll
        for (int j = 0; j < 4; j++)
            go[(ry + i) * NM + tx + 16 * j] = acc[i][j];
    if (tid < 64) g_rows[chunk][which][b][tid] = rowAcc;
}

// ---------------------------------------------------------------------------
// K2: cov assembly + coupled Newton-Schulz. grid = 128, block = 256.
// All of Y, Z, T are symmetric (polynomials of the same SPD matrix), so the
// row-indexed operand is read as a column float4: per k, 2 LDS.128 + 16 FFMA.
// Iter 0: Z=I so T = 1.5I - 0.5Y and Z1 = T (bitwise equal to the matmuls).
// Last iter: only the needed factor (w=0 -> Z, w=1 -> Y) is updated.
// ---------------------------------------------------------------------------
__global__ __launch_bounds__(256)
void k_ns()
{
    const int w = blockIdx.x >> 6;
    const int b = blockIdx.x & 63;

    __shared__ __align__(16) float sY[NM * NM];
    __shared__ __align__(16) float sZ[NM * NM];
    __shared__ __align__(16) float sT[NM * NM];

    const int tid = threadIdx.x;
    const int tx = tid & 15, ty = tid >> 4;
    const int ry = ty * 4, cx = tx * 4;

    // means into sT[0..63] (temp) and global
    if (tid < NM) {
        float s = 0.f;
#pragma unroll
        for (int ch = 0; ch < KSPLIT; ch++) s += g_rows[ch][w][b][tid];
        float m = s * (1.f / (float)HW);
        sT[tid] = m;
        g_mean[w][b][tid] = m;
    }
    __syncthreads();

    // cov -> sY, accumulate Frobenius^2
    float sq = 0.f;
#pragma unroll
    for (int i = 0; i < 4; i++) {
        float mr = sT[ry + i];
#pragma unroll
        for (int j = 0; j < 4; j++) {
            int r = ry + i, c = cx + j;
            int idx = r * NM + c;
            float g = 0.f;
#pragma unroll
            for (int ch = 0; ch < KSPLIT; ch++) g += g_gram[ch][w][b][idx];
            float cv = (g - (float)HW * mr * sT[c]) * (1.f / (float)(HW - 1));
            if (r == c) cv += EPSV;
            sY[idx] = cv;
            sq += cv * cv;
        }
    }
    __syncthreads();              // means consumed
    sT[tid] = sq;
    __syncthreads();
#pragma unroll
    for (int s = 128; s > 0; s >>= 1) {
        if (tid < s) sT[tid] += sT[tid + s];
        __syncthreads();
    }
    const float norm = sqrtf(sT[0]);
    const float invn = 1.f / norm;
    __syncthreads();

    // Y = A/norm (Z = I handled by iter-0 shortcut)
#pragma unroll
    for (int i = 0; i < 4; i++)
#pragma unroll
        for (int j = 0; j < 4; j++)
            sY[(ry + i) * NM + cx + j] *= invn;
    __syncthreads();

    // ---- iteration 0: T = 1.5I - 0.5*Y ; Ynew = Y@T ; Z1 = T ----
#pragma unroll
    for (int i = 0; i < 4; i++)
#pragma unroll
        for (int j = 0; j < 4; j++) {
            int r = ry + i, c = cx + j;
            sT[r * NM + c] = ((r == c) ? 1.5f : 0.f) - 0.5f * sY[r * NM + c];
        }
    __syncthreads();
    {
        float ya[4][4];
#pragma unroll
        for (int i = 0; i < 4; i++)
#pragma unroll
            for (int j = 0; j < 4; j++) ya[i][j] = 0.f;
#pragma unroll 4
        for (int k = 0; k < NM; k++) {
            float4 av = *reinterpret_cast<const float4*>(&sY[k * NM + ry]); // Y sym
            float4 bv = *reinterpret_cast<const float4*>(&sT[k * NM + cx]);
            OUTER16(ya, av, bv);
        }
        __syncthreads();
#pragma unroll
        for (int i = 0; i < 4; i++)
#pragma unroll
            for (int j = 0; j < 4; j++) {
                int idx = (ry + i) * NM + cx + j;
                sY[idx] = ya[i][j];
                sZ[idx] = sT[idx];
            }
        __syncthreads();
    }

    // ---- iterations 1..9 ----
    for (int it = 1; it < NSI; it++) {
        // T = 1.5I - 0.5*Z@Y
        float ta[4][4];
#pragma unroll
        for (int i = 0; i < 4; i++)
#pragma unroll
            for (int j = 0; j < 4; j++) ta[i][j] = 0.f;
#pragma unroll 4
        for (int k = 0; k < NM; k++) {
            float4 av = *reinterpret_cast<const float4*>(&sZ[k * NM + ry]); // Z sym
            float4 bv = *reinterpret_cast<const float4*>(&sY[k * NM + cx]);
            OUTER16(ta, av, bv);
        }
#pragma unroll
        for (int i = 0; i < 4; i++)
#pragma unroll
            for (int j = 0; j < 4; j++) {
                int r = ry + i, c = cx + j;
                sT[r * NM + c] = ((r == c) ? 1.5f : 0.f) - 0.5f * ta[i][j];
            }
        __syncthreads();

        if (it < NSI - 1) {
            // Ynew = Y@T ; Znew = T@Z (combined)
            float ya[4][4], za[4][4];
#pragma unroll
            for (int i = 0; i < 4; i++)
#pragma unroll
                for (int j = 0; j < 4; j++) { ya[i][j] = 0.f; za[i][j] = 0.f; }
#pragma unroll 4
            for (int k = 0; k < NM; k++) {
                float4 ay = *reinterpret_cast<const float4*>(&sY[k * NM + ry]);
                float4 bt = *reinterpret_cast<const float4*>(&sT[k * NM + cx]);
                OUTER16(ya, ay, bt);
                float4 at = *reinterpret_cast<const float4*>(&sT[k * NM + ry]);
                float4 bz = *reinterpret_cast<const float4*>(&sZ[k * NM + cx]);
                OUTER16(za, at, bz);
            }
            __syncthreads();
#pragma unroll
            for (int i = 0; i < 4; i++)
#pragma unroll
                for (int j = 0; j < 4; j++) {
                    int idx = (ry + i) * NM + cx + j;
                    sY[idx] = ya[i][j];
                    sZ[idx] = za[i][j];
                }
            __syncthreads();
        } else if (w == 1) {
            // only Y needed
            float ya[4][4];
#pragma unroll
            for (int i = 0; i < 4; i++)
#pragma unroll
                for (int j = 0; j < 4; j++) ya[i][j] = 0.f;
#pragma unroll 4
            for (int k = 0; k < NM; k++) {
                float4 ay = *reinterpret_cast<const float4*>(&sY[k * NM + ry]);
                float4 bt = *reinterpret_cast<const float4*>(&sT[k * NM + cx]);
                OUTER16(ya, ay, bt);
            }
            __syncthreads();
#pragma unroll
            for (int i = 0; i < 4; i++)
#pragma unroll
                for (int j = 0; j < 4; j++)
                    sY[(ry + i) * NM + cx + j] = ya[i][j];
            __syncthreads();
        } else {
            // only Z needed
            float za[4][4];
#pragma unroll
            for (int i = 0; i < 4; i++)
#pragma unroll
                for (int j = 0; j < 4; j++) za[i][j] = 0.f;
#pragma unroll 4
            for (int k = 0; k < NM; k++) {
                float4 at = *reinterpret_cast<const float4*>(&sT[k * NM + ry]);
                float4 bz = *reinterpret_cast<const float4*>(&sZ[k * NM + cx]);
                OUTER16(za, at, bz);
            }
            __syncthreads();
#pragma unroll
            for (int i = 0; i < 4; i++)
#pragma unroll
                for (int j = 0; j < 4; j++)
                    sZ[(ry + i) * NM + cx + j] = za[i][j];
            __syncthreads();
        }
    }

    const float sq_n  = sqrtf(norm);
    const float scale = (w == 0) ? (1.f / sq_n) : sq_n;
    const float* __restrict__ src = (w == 0) ? sZ : sY;
    float* __restrict__ dst = g_ns[w][b];
#pragma unroll
    for (int i = 0; i < 4; i++)
#pragma unroll
        for (int j = 0; j < 4; j++) {
            int idx = (ry + i) * NM + cx + j;
            dst[idx] = src[idx] * scale;
        }
}

// ---------------------------------------------------------------------------
// K3: Mt = (cov_b_sqrt @ cov_c_invsqrt)^T ; v = mu_B - M*mu_A. grid=64, blk=256.
// Both factors symmetric -> a-side read as column float4.
// ---------------------------------------------------------------------------
__global__ __launch_bounds__(256)
void k_mix()
{
    const int b = blockIdx.x;
    __shared__ __align__(16) float sA[NM * NM];
    __shared__ __align__(16) float sB[NM * NM];
    __shared__ __align__(16) float sCt[NM * NM];
    const int tid = threadIdx.x;
    const int tx = tid & 15, ty = tid >> 4;
    const int ry = ty * 4, cx = tx * 4;

#pragma unroll
    for (int l = 0; l < 4; l++) {
        int idx4 = (tid + l * 256) * 4;
        *reinterpret_cast<float4*>(&sA[idx4]) =
            *reinterpret_cast<const float4*>(&g_ns[1][b][idx4]);
        *reinterpret_cast<float4*>(&sB[idx4]) =
            *reinterpret_cast<const float4*>(&g_ns[0][b][idx4]);
    }
    __syncthreads();

    float acc[4][4];
#pragma unroll
    for (int i = 0; i < 4; i++)
#pragma unroll
        for (int j = 0; j < 4; j++) acc[i][j] = 0.f;

#pragma unroll 4
    for (int k = 0; k < NM; k++) {
        float4 av = *reinterpret_cast<const float4*>(&sA[k * NM + ry]); // A sym
        float4 bv = *reinterpret_cast<const float4*>(&sB[k * NM + cx]);
        OUTER16(acc, av, bv);
    }
#pragma unroll
    for (int i = 0; i < 4; i++)
#pragma unroll
        for (int j = 0; j < 4; j++) {
            int tidx = (cx + j) * NM + (ry + i);   // transposed
            sCt[tidx]      = acc[i][j];
            g_Mt[b][tidx]  = acc[i][j];
        }
    __syncthreads();

    if (tid < NM) {
        float mv = g_mean[1][b][tid];
#pragma unroll 8
        for (int k = 0; k < NM; k++)
            mv -= sCt[k * NM + tid] * g_mean[0][b][k];   // M[tid][k]
        g_v[b][tid] = mv;
    }
}

// ---------------------------------------------------------------------------
// K4: out = alpha*(M @ c_A + v) + (1-alpha)*c_A. grid = NB*16, block = 256.
// a = Mt column float4, b = X tile column float4: per k, 2 LDS.128 + 16 FFMA.
// Register-prefetched X tiles.
// ---------------------------------------------------------------------------
__global__ __launch_bounds__(256)
void k_out(const float* __restrict__ cAp, const float* __restrict__ alphap,
           float* __restrict__ outp)
{
    const int b  = blockIdx.x >> 4;
    const int s0 = (blockIdx.x & 15) * 256;

    __shared__ __align__(16) float sMt[NM * NM];
    __shared__ __align__(16) float xt[NM * NM];

    const int tid = threadIdx.x;
    const int tx = tid & 15, ty = tid >> 4;
    const int ry = ty * 4, sx = tx * 4;

    const float alpha = __ldg(alphap);
    const float beta  = 1.f - alpha;
    const float* __restrict__ X = cAp  + (size_t)b * NM * HW + s0;
    float* __restrict__ O       = outp + (size_t)b * NM * HW + s0;

#pragma unroll
    for (int l = 0; l < 4; l++) {
        int idx4 = (tid + l * 256) * 4;
        *reinterpret_cast<float4*>(&sMt[idx4]) =
            *reinterpret_cast<const float4*>(&g_Mt[b][idx4]);
    }
    float vr[4];
#pragma unroll
    for (int i = 0; i < 4; i++) vr[i] = g_v[b][ry + i];

    // prefetch tile 0
    float4 pf[4];
#pragma unroll
    for (int l = 0; l < 4; l++)
        pf[l] = *reinterpret_cast<const float4*>(
            X + (size_t)(ty + 16 * l) * HW + 4 * tx);

    for (int sc = 0; sc < 4; sc++) {
        __syncthreads();   // previous tile consumed (covers sMt load on sc==0)
#pragma unroll
        for (int l = 0; l < 4; l++)
            *reinterpret_cast<float4*>(&xt[(ty + 16 * l) * NM + 4 * tx]) = pf[l];
        if (sc < 3) {
#pragma unroll
            for (int l = 0; l < 4; l++)
                pf[l] = *reinterpret_cast<const float4*>(
                    X + (size_t)(ty + 16 * l) * HW + (sc + 1) * 64 + 4 * tx);
        }
        __syncthreads();

        float acc[4][4];
#pragma unroll
        for (int i = 0; i < 4; i++)
#pragma unroll
            for (int j = 0; j < 4; j++) acc[i][j] = 0.f;

#pragma unroll 8
        for (int k = 0; k < NM; k++) {
            float4 av = *reinterpret_cast<const float4*>(&sMt[k * NM + ry]);
            float4 bv = *reinterpret_cast<const float4*>(&xt[k * NM + sx]);
            OUTER16(acc, av, bv);
        }

#pragma unroll
        for (int i = 0; i < 4; i++) {
            float4 cv = *reinterpret_cast<const float4*>(&xt[(ry + i) * NM + sx]);
            float4 o;
            o.x = alpha * (acc[i][0] + vr[i]) + beta * cv.x;
            o.y = alpha * (acc[i][1] + vr[i]) + beta * cv.y;
            o.z = alpha * (acc[i][2] + vr[i]) + beta * cv.z;
            o.w = alpha * (acc[i][3] + vr[i]) + beta * cv.w;
            *reinterpret_cast<float4*>(
                &O[(size_t)(ry + i) * HW + sc * 64 + sx]) = o;
        }
    }
}

// ---------------------------------------------------------------------------
extern "C" void kernel_launch(void* const* d_in, const int* in_sizes, int n_in,
                              void* d_out, int out_size)
{
    const float* cA    = (const float*)d_in[0];
    const float* sB    = (const float*)d_in[1];
    const float* alpha = (const float*)d_in[2];
    float* out         = (float*)d_out;

    k_gram<<<KSPLIT * 128, 256>>>(cA, sB);
    k_ns  <<<128, 256>>>();
    k_mix <<<NB, 256>>>();
    k_out <<<NB * 16, 256>>>(cA, alpha, out);
}

// round 10
// speedup vs baseline: 1.5895x; 1.3235x over previous
#include <cuda_runtime.h>
#include <cuda_bf16.h>
#include <cstdint>

#define NM 64
#define HW 4096
#define NB 64
#define KSPLIT 8
#define KCHUNK (HW / KSPLIT)
#define NSI 10
#define EPSV 1e-5f
#define BTS 72   // bf16 tile row stride (144 B: ldmatrix conflict-free)

__device__ __align__(16) float g_gram[KSPLIT][2][NB][NM * NM];
__device__ __align__(16) float g_rows[KSPLIT][2][NB][NM];
__device__ __align__(16) float g_mean[2][NB][NM];
__device__ __align__(16) float g_ns[2][NB][NM * NM];
__device__ __align__(16) float g_Mt[NB][NM * NM];
__device__ __align__(16) float g_v[NB][NM];

// ---- warp-MMA helpers (baseline PTX, no arch suffix needed) ----
__device__ __forceinline__ uint32_t smem_u32(const void* p) {
    uint32_t a;
    asm("{ .reg .u64 t; cvta.to.shared.u64 t, %1; cvt.u32.u64 %0, t; }"
        : "=r"(a) : "l"(p));
    return a;
}
__device__ __forceinline__ void ldm4(uint32_t r[4], uint32_t addr) {
    asm volatile("ldmatrix.sync.aligned.m8n8.x4.shared.b16 {%0,%1,%2,%3}, [%4];"
                 : "=r"(r[0]), "=r"(r[1]), "=r"(r[2]), "=r"(r[3]) : "r"(addr));
}
__device__ __forceinline__ void mma16816(float d[4], const uint32_t a[4],
                                         const uint32_t b[2]) {
    asm volatile(
        "mma.sync.aligned.m16n8k16.row.col.f32.bf16.bf16.f32 "
        "{%0,%1,%2,%3}, {%4,%5,%6,%7}, {%8,%9}, {%0,%1,%2,%3};"
        : "+f"(d[0]), "+f"(d[1]), "+f"(d[2]), "+f"(d[3])
        : "r"(a[0]), "r"(a[1]), "r"(a[2]), "r"(a[3]), "r"(b[0]), "r"(b[1]));
}

#define OUTER16(acc, av, bv)                                                  \
    acc[0][0] += av.x * bv.x; acc[0][1] += av.x * bv.y;                       \
    acc[0][2] += av.x * bv.z; acc[0][3] += av.x * bv.w;                       \
    acc[1][0] += av.y * bv.x; acc[1][1] += av.y * bv.y;                       \
    acc[1][2] += av.y * bv.z; acc[1][3] += av.y * bv.w;                       \
    acc[2][0] += av.z * bv.x; acc[2][1] += av.z * bv.y;                       \
    acc[2][2] += av.z * bv.z; acc[2][3] += av.z * bv.w;                       \
    acc[3][0] += av.w * bv.x; acc[3][1] += av.w * bv.y;                       \
    acc[3][2] += av.w * bv.z; acc[3][3] += av.w * bv.w;

// ---------------------------------------------------------------------------
// K1: Gram via warp mma.sync bf16 3-split. grid = KSPLIT*128, block = 256.
// bid: pair = bid&127 (which = pair>>6, b = pair&63), chunk = bid>>7.
// Each 64-k sub-tile: fp32 -> bf16 hi/lo smem (stride BTS), then 8 warps
// (warp w: rows (w>>1)*16.., cols (w&1)*32..) do 4 k16-steps x 12 MMA.
// ---------------------------------------------------------------------------
__global__ __launch_bounds__(256)
void k_gram_mma(const float* __restrict__ cAp, const float* __restrict__ sBp)
{
    const int pair  = blockIdx.x & 127;
    const int chunk = blockIdx.x >> 7;
    const int which = pair >> 6;
    const int b     = pair & 63;
    const float* __restrict__ X =
        (which ? sBp : cAp) + (size_t)b * NM * HW + chunk * KCHUNK;

    __shared__ __align__(16) __nv_bfloat16 sHi[NM * BTS];
    __shared__ __align__(16) __nv_bfloat16 sLo[NM * BTS];

    const int tid  = threadIdx.x;
    const int wid  = tid >> 5;
    const int lane = tid & 31;

    // conversion mapping: 16 floats per thread
    const int crow = tid >> 2;
    const int ckb  = (tid & 3) * 16;
    const float* __restrict__ Xrow = X + (size_t)crow * HW + ckb;

    // warp tile
    const int mi = (wid >> 1) * 16;
    const int nj = (wid & 1) * 32;

    const uint32_t hi_u = smem_u32(sHi);
    const uint32_t lo_u = smem_u32(sLo);

    // ldmatrix lane addresses (element offsets; *2 for bytes)
    const int a_off = (mi + (lane & 15)) * BTS + ((lane & 16) ? 8 : 0);
    const int b_off0 = (nj + (lane & 7) + ((lane & 16) ? 8 : 0)) * BTS
                     + ((lane & 8) ? 8 : 0);
    const uint32_t aH = hi_u + a_off * 2,            aL = lo_u + a_off * 2;
    const uint32_t bH0 = hi_u + b_off0 * 2,          bL0 = lo_u + b_off0 * 2;
    const uint32_t bH1 = bH0 + 16 * BTS * 2,         bL1 = bL0 + 16 * BTS * 2;

    float acc[4][4];
#pragma unroll
    for (int i = 0; i < 4; i++)
#pragma unroll
        for (int j = 0; j < 4; j++) acc[i][j] = 0.f;
    float rowAcc = 0.f;

    for (int kt = 0; kt < KCHUNK; kt += 64) {
        float4 v[4];
#pragma unroll
        for (int s = 0; s < 4; s++)
            v[s] = *reinterpret_cast<const float4*>(Xrow + kt + s * 4);

        __syncthreads();   // previous tile fully consumed by MMAs

        uint32_t h[8], l[8];
#pragma unroll
        for (int s = 0; s < 4; s++) {
            float4 x = v[s];
            rowAcc += x.x + x.y + x.z + x.w;
            __nv_bfloat16 h0 = __float2bfloat16(x.x), h1 = __float2bfloat16(x.y);
            __nv_bfloat16 h2 = __float2bfloat16(x.z), h3 = __float2bfloat16(x.w);
            __nv_bfloat16 l0 = __float2bfloat16(x.x - __bfloat162float(h0));
            __nv_bfloat16 l1 = __float2bfloat16(x.y - __bfloat162float(h1));
            __nv_bfloat16 l2 = __float2bfloat16(x.z - __bfloat162float(h2));
            __nv_bfloat16 l3 = __float2bfloat16(x.w - __bfloat162float(h3));
            h[2*s]   = (uint32_t)__bfloat16_as_ushort(h0) |
                       ((uint32_t)__bfloat16_as_ushort(h1) << 16);
            h[2*s+1] = (uint32_t)__bfloat16_as_ushort(h2) |
                       ((uint32_t)__bfloat16_as_ushort(h3) << 16);
            l[2*s]   = (uint32_t)__bfloat16_as_ushort(l0) |
                       ((uint32_t)__bfloat16_as_ushort(l1) << 16);
            l[2*s+1] = (uint32_t)__bfloat16_as_ushort(l2) |
                       ((uint32_t)__bfloat16_as_ushort(l3) << 16);
        }
        {
            __nv_bfloat16* hp = &sHi[crow * BTS + ckb];
            __nv_bfloat16* lp = &sLo[crow * BTS + ckb];
            *reinterpret_cast<uint4*>(hp)     = make_uint4(h[0], h[1], h[2], h[3]);
            *reinterpret_cast<uint4*>(hp + 8) = make_uint4(h[4], h[5], h[6], h[7]);
            *reinterpret_cast<uint4*>(lp)     = make_uint4(l[0], l[1], l[2], l[3]);
            *reinterpret_cast<uint4*>(lp + 8) = make_uint4(l[4], l[5], l[6], l[7]);
        }
        __syncthreads();

#pragma unroll
        for (int k0 = 0; k0 < 64; k0 += 16) {
            uint32_t ah[4], al[4], bh[8], bl[8];
            ldm4(ah, aH + k0 * 2);
            ldm4(al, aL + k0 * 2);
            ldm4(bh,     bH0 + k0 * 2);
            ldm4(bh + 4, bH1 + k0 * 2);
            ldm4(bl,     bL0 + k0 * 2);
            ldm4(bl + 4, bL1 + k0 * 2);
#pragma unroll
            for (int nt = 0; nt < 4; nt++) {
                mma16816(acc[nt], ah, &bh[2 * nt]);   // hi*hi
                mma16816(acc[nt], ah, &bl[2 * nt]);   // hi*lo
                mma16816(acc[nt], al, &bh[2 * nt]);   // lo*hi
            }
        }
    }

    // row sums: reduce the 4 lanes sharing a row
    rowAcc += __shfl_down_sync(0xffffffffu, rowAcc, 1);
    rowAcc += __shfl_down_sync(0xffffffffu, rowAcc, 2);
    if ((tid & 3) == 0) g_rows[chunk][which][b][crow] = rowAcc;

    // epilogue: D fragment -> g_gram. thread (g = lane>>2, t = lane&3):
    // d0,d1 = (mi+g, cn+2t..+1); d2,d3 = (mi+g+8, cn+2t..+1)
    {
        float* __restrict__ go = g_gram[chunk][which][b];
        const int g = lane >> 2, t = lane & 3;
#pragma unroll
        for (int nt = 0; nt < 4; nt++) {
            const int cn = nj + 8 * nt + 2 * t;
            *reinterpret_cast<float2*>(go + (mi + g)     * NM + cn) =
                make_float2(acc[nt][0], acc[nt][1]);
            *reinterpret_cast<float2*>(go + (mi + g + 8) * NM + cn) =
                make_float2(acc[nt][2], acc[nt][3]);
        }
    }
}

// ---------------------------------------------------------------------------
// K2: cov assembly + coupled Newton-Schulz (unchanged, passing).
// ---------------------------------------------------------------------------
__global__ __launch_bounds__(256)
void k_ns()
{
    const int w = blockIdx.x >> 6;
    const int b = blockIdx.x & 63;

    __shared__ __align__(16) float sY[NM * NM];
    __shared__ __align__(16) float sZ[NM * NM];
    __shared__ __align__(16) float sT[NM * NM];

    const int tid = threadIdx.x;
    const int tx = tid & 15, ty = tid >> 4;
    const int ry = ty * 4, cx = tx * 4;

    if (tid < NM) {
        float s = 0.f;
#pragma unroll
        for (int ch = 0; ch < KSPLIT; ch++) s += g_rows[ch][w][b][tid];
        float m = s * (1.f / (float)HW);
        sT[tid] = m;
        g_mean[w][b][tid] = m;
    }
    __syncthreads();

    float sq = 0.f;
#pragma unroll
    for (int i = 0; i < 4; i++) {
        float mr = sT[ry + i];
#pragma unroll
        for (int j = 0; j < 4; j++) {
            int r = ry + i, c = cx + j, idx = r * NM + c;
            float g = 0.f;
#pragma unroll
            for (int ch = 0; ch < KSPLIT; ch++) g += g_gram[ch][w][b][idx];
            float cv = (g - (float)HW * mr * sT[c]) * (1.f / (float)(HW - 1));
            if (r == c) cv += EPSV;
            sY[idx] = cv;
            sq += cv * cv;
        }
    }
    __syncthreads();
    sT[tid] = sq;
    __syncthreads();
#pragma unroll
    for (int s = 128; s > 0; s >>= 1) {
        if (tid < s) sT[tid] += sT[tid + s];
        __syncthreads();
    }
    const float norm = sqrtf(sT[0]);
    const float invn = 1.f / norm;
    __syncthreads();

#pragma unroll
    for (int i = 0; i < 4; i++)
#pragma unroll
        for (int j = 0; j < 4; j++)
            sY[(ry + i) * NM + cx + j] *= invn;
    __syncthreads();

#pragma unroll
    for (int i = 0; i < 4; i++)
#pragma unroll
        for (int j = 0; j < 4; j++) {
            int r = ry + i, c = cx + j;
            sT[r * NM + c] = ((r == c) ? 1.5f : 0.f) - 0.5f * sY[r * NM + c];
        }
    __syncthreads();
    {
        float ya[4][4];
#pragma unroll
        for (int i = 0; i < 4; i++)
#pragma unroll
            for (int j = 0; j < 4; j++) ya[i][j] = 0.f;
#pragma unroll 4
        for (int k = 0; k < NM; k++) {
            float4 av = *reinterpret_cast<const float4*>(&sY[k * NM + ry]);
            float4 bv = *reinterpret_cast<const float4*>(&sT[k * NM + cx]);
            OUTER16(ya, av, bv);
        }
        __syncthreads();
#pragma unroll
        for (int i = 0; i < 4; i++)
#pragma unroll
            for (int j = 0; j < 4; j++) {
                int idx = (ry + i) * NM + cx + j;
                sY[idx] = ya[i][j];
                sZ[idx] = sT[idx];
            }
        __syncthreads();
    }

    for (int it = 1; it < NSI; it++) {
        float ta[4][4];
#pragma unroll
        for (int i = 0; i < 4; i++)
#pragma unroll
            for (int j = 0; j < 4; j++) ta[i][j] = 0.f;
#pragma unroll 4
        for (int k = 0; k < NM; k++) {
            float4 av = *reinterpret_cast<const float4*>(&sZ[k * NM + ry]);
            float4 bv = *reinterpret_cast<const float4*>(&sY[k * NM + cx]);
            OUTER16(ta, av, bv);
        }
#pragma unroll
        for (int i = 0; i < 4; i++)
#pragma unroll
            for (int j = 0; j < 4; j++) {
                int r = ry + i, c = cx + j;
                sT[r * NM + c] = ((r == c) ? 1.5f : 0.f) - 0.5f * ta[i][j];
            }
        __syncthreads();

        if (it < NSI - 1) {
            float ya[4][4], za[4][4];
#pragma unroll
            for (int i = 0; i < 4; i++)
#pragma unroll
                for (int j = 0; j < 4; j++) { ya[i][j] = 0.f; za[i][j] = 0.f; }
#pragma unroll 4
            for (int k = 0; k < NM; k++) {
                float4 ay = *reinterpret_cast<const float4*>(&sY[k * NM + ry]);
                float4 bt = *reinterpret_cast<const float4*>(&sT[k * NM + cx]);
                OUTER16(ya, ay, bt);
                float4 at = *reinterpret_cast<const float4*>(&sT[k * NM + ry]);
                float4 bz = *reinterpret_cast<const float4*>(&sZ[k * NM + cx]);
                OUTER16(za, at, bz);
            }
            __syncthreads();
#pragma unroll
            for (int i = 0; i < 4; i++)
#pragma unroll
                for (int j = 0; j < 4; j++) {
                    int idx = (ry + i) * NM + cx + j;
                    sY[idx] = ya[i][j];
                    sZ[idx] = za[i][j];
                }
            __syncthreads();
        } else if (w == 1) {
            float ya[4][4];
#pragma unroll
            for (int i = 0; i < 4; i++)
#pragma unroll
                for (int j = 0; j < 4; j++) ya[i][j] = 0.f;
#pragma unroll 4
            for (int k = 0; k < NM; k++) {
                float4 ay = *reinterpret_cast<const float4*>(&sY[k * NM + ry]);
                float4 bt = *reinterpret_cast<const float4*>(&sT[k * NM + cx]);
                OUTER16(ya, ay, bt);
            }
            __syncthreads();
#pragma unroll
            for (int i = 0; i < 4; i++)
#pragma unroll
                for (int j = 0; j < 4; j++)
                    sY[(ry + i) * NM + cx + j] = ya[i][j];
            __syncthreads();
        } else {
            float za[4][4];
#pragma unroll
            for (int i = 0; i < 4; i++)
#pragma unroll
                for (int j = 0; j < 4; j++) za[i][j] = 0.f;
#pragma unroll 4
            for (int k = 0; k < NM; k++) {
                float4 at = *reinterpret_cast<const float4*>(&sT[k * NM + ry]);
                float4 bz = *reinterpret_cast<const float4*>(&sZ[k * NM + cx]);
                OUTER16(za, at, bz);
            }
            __syncthreads();
#pragma unroll
            for (int i = 0; i < 4; i++)
#pragma unroll
                for (int j = 0; j < 4; j++)
                    sZ[(ry + i) * NM + cx + j] = za[i][j];
            __syncthreads();
        }
    }

    const float sq_n  = sqrtf(norm);
    const float scale = (w == 0) ? (1.f / sq_n) : sq_n;
    const float* __restrict__ src = (w == 0) ? sZ : sY;
    float* __restrict__ dst = g_ns[w][b];
#pragma unroll
    for (int i = 0; i < 4; i++)
#pragma unroll
        for (int j = 0; j < 4; j++) {
            int idx = (ry + i) * NM + cx + j;
            dst[idx] = src[idx] * scale;
        }
}

// ---------------------------------------------------------------------------
// K3 (unchanged)
// ---------------------------------------------------------------------------
__global__ __launch_bounds__(256)
void k_mix()
{
    const int b = blockIdx.x;
    __shared__ __align__(16) float sA[NM * NM];
    __shared__ __align__(16) float sB[NM * NM];
    __shared__ __align__(16) float sCt[NM * NM];
    const int tid = threadIdx.x;
    const int tx = tid & 15, ty = tid >> 4;
    const int ry = ty * 4, cx = tx * 4;

#pragma unroll
    for (int l = 0; l < 4; l++) {
        int idx4 = (tid + l * 256) * 4;
        *reinterpret_cast<float4*>(&sA[idx4]) =
            *reinterpret_cast<const float4*>(&g_ns[1][b][idx4]);
        *reinterpret_cast<float4*>(&sB[idx4]) =
            *reinterpret_cast<const float4*>(&g_ns[0][b][idx4]);
    }
    __syncthreads();

    float acc[4][4];
#pragma unroll
    for (int i = 0; i < 4; i++)
#pragma unroll
        for (int j = 0; j < 4; j++) acc[i][j] = 0.f;
#pragma unroll 4
    for (int k = 0; k < NM; k++) {
        float4 av = *reinterpret_cast<const float4*>(&sA[k * NM + ry]);
        float4 bv = *reinterpret_cast<const float4*>(&sB[k * NM + cx]);
        OUTER16(acc, av, bv);
    }
#pragma unroll
    for (int i = 0; i < 4; i++)
#pragma unroll
        for (int j = 0; j < 4; j++) {
            int tidx = (cx + j) * NM + (ry + i);
            sCt[tidx]     = acc[i][j];
            g_Mt[b][tidx] = acc[i][j];
        }
    __syncthreads();

    if (tid < NM) {
        float mv = g_mean[1][b][tid];
#pragma unroll 8
        for (int k = 0; k < NM; k++)
            mv -= sCt[k * NM + tid] * g_mean[0][b][k];
        g_v[b][tid] = mv;
    }
}

// ---------------------------------------------------------------------------
// K4 (unchanged)
// ---------------------------------------------------------------------------
__global__ __launch_bounds__(256)
void k_out(const float* __restrict__ cAp, const float* __restrict__ alphap,
           float* __restrict__ outp)
{
    const int b  = blockIdx.x >> 4;
    const int s0 = (blockIdx.x & 15) * 256;

    __shared__ __align__(16) float sMt[NM * NM];
    __shared__ __align__(16) float xt[NM * NM];

    const int tid = threadIdx.x;
    const int tx = tid & 15, ty = tid >> 4;
    const int ry = ty * 4, sx = tx * 4;

    const float alpha = __ldg(alphap);
    const float beta  = 1.f - alpha;
    const float* __restrict__ X = cAp  + (size_t)b * NM * HW + s0;
    float* __restrict__ O       = outp + (size_t)b * NM * HW + s0;

#pragma unroll
    for (int l = 0; l < 4; l++) {
        int idx4 = (tid + l * 256) * 4;
        *reinterpret_cast<float4*>(&sMt[idx4]) =
            *reinterpret_cast<const float4*>(&g_Mt[b][idx4]);
    }
    float vr[4];
#pragma unroll
    for (int i = 0; i < 4; i++) vr[i] = g_v[b][ry + i];

    float4 pf[4];
#pragma unroll
    for (int l = 0; l < 4; l++)
        pf[l] = *reinterpret_cast<const float4*>(
            X + (size_t)(ty + 16 * l) * HW + 4 * tx);

    for (int sc = 0; sc < 4; sc++) {
        __syncthreads();
#pragma unroll
        for (int l = 0; l < 4; l++)
            *reinterpret_cast<float4*>(&xt[(ty + 16 * l) * NM + 4 * tx]) = pf[l];
        if (sc < 3) {
#pragma unroll
            for (int l = 0; l < 4; l++)
                pf[l] = *reinterpret_cast<const float4*>(
                    X + (size_t)(ty + 16 * l) * HW + (sc + 1) * 64 + 4 * tx);
        }
        __syncthreads();

        float acc[4][4];
#pragma unroll
        for (int i = 0; i < 4; i++)
#pragma unroll
            for (int j = 0; j < 4; j++) acc[i][j] = 0.f;
#pragma unroll 8
        for (int k = 0; k < NM; k++) {
            float4 av = *reinterpret_cast<const float4*>(&sMt[k * NM + ry]);
            float4 bv = *reinterpret_cast<const float4*>(&xt[k * NM + sx]);
            OUTER16(acc, av, bv);
        }

#pragma unroll
        for (int i = 0; i < 4; i++) {
            float4 cv = *reinterpret_cast<const float4*>(&xt[(ry + i) * NM + sx]);
            float4 o;
            o.x = alpha * (acc[i][0] + vr[i]) + beta * cv.x;
            o.y = alpha * (acc[i][1] + vr[i]) + beta * cv.y;
            o.z = alpha * (acc[i][2] + vr[i]) + beta * cv.z;
            o.w = alpha * (acc[i][3] + vr[i]) + beta * cv.w;
            *reinterpret_cast<float4*>(
                &O[(size_t)(ry + i) * HW + sc * 64 + sx]) = o;
        }
    }
}

// ---------------------------------------------------------------------------
extern "C" void kernel_launch(void* const* d_in, const int* in_sizes, int n_in,
                              void* d_out, int out_size)
{
    const float* cA    = (const float*)d_in[0];
    const float* sB    = (const float*)d_in[1];
    const float* alpha = (const float*)d_in[2];
    float* out         = (float*)d_out;

    k_gram_mma<<<KSPLIT * 128, 256>>>(cA, sB);
    k_ns  <<<128, 256>>>();
    k_mix <<<NB, 256>>>();
    k_out <<<NB * 16, 256>>>(cA, alpha, out);
}